// round 6
// baseline (speedup 1.0000x reference)
#include <cuda_runtime.h>
#include <math.h>

#define NNODES 100000
#define BATCH  4096
#define MDIM   256
#define G3DIM  768
#define INENC  515
#define NT     512
#define BK     16

typedef unsigned long long u64;

// ---------------- device scratch (rebuilt every launch; graph-replay safe) -----------
__device__ int      g_ncnt[NNODES];
__device__ int      g_nbuck[NNODES * BK];
__device__ int      g_pred[2 * BATCH];
__device__ float    g_F[2 * BATCH];
__device__ int      g_evlist[BATCH];
__device__ int      g_lvl_start[BATCH + 2];
__device__ int      g_nlevels;
__device__ unsigned g_bar_count = 0;
__device__ unsigned g_bar_gen   = 0;

__device__ int   g_pS[BATCH], g_pD[BATCH];
__device__ float g_pFs[BATCH], g_pFd[BATCH];
__device__ float g_pEF[BATCH * 3];

__device__ __align__(16) float g_H1 [BATCH * MDIM];
__device__ __align__(16) float g_GI [BATCH * G3DIM];
__device__ __align__(16) float g_GHs[BATCH * G3DIM];
__device__ __align__(16) float g_GHd[BATCH * G3DIM];

// transposed+packed weights: layout [k4][c][4] (16B per (k4,c))
__device__ __align__(16) float g_W1tA[MDIM * MDIM];
__device__ __align__(16) float g_W1tB[MDIM * MDIM];
__device__ __align__(16) float g_W1te[3 * MDIM];
__device__ __align__(16) float g_whht[G3DIM * MDIM];
__device__ __align__(16) float g_Wct [G3DIM * MDIM];
__device__ __align__(16) float g_bc  [G3DIM];

// ---------------- software grid barrier (1 block/SM) ---------------------------------
__device__ __forceinline__ void grid_sync() {
    __syncthreads();
    if (threadIdx.x == 0) {
        __threadfence();
        unsigned gen = *((volatile unsigned*)&g_bar_gen);
        if (atomicAdd(&g_bar_count, 1u) == gridDim.x - 1u) {
            *((volatile unsigned*)&g_bar_count) = 0u;
            __threadfence();
            atomicAdd(&g_bar_gen, 1u);
        } else {
            while (*((volatile unsigned*)&g_bar_gen) == gen) { __nanosleep(64); }
        }
        __threadfence();
    }
    __syncthreads();
}

// ---------------- packed f32x2 helpers ------------------------------------------------
__device__ __forceinline__ u64 ffma2(u64 a, u64 b, u64 c) {
    u64 d;
    asm("fma.rn.f32x2 %0, %1, %2, %3;" : "=l"(d) : "l"(a), "l"(b), "l"(c));
    return d;
}
__device__ __forceinline__ float pair_sum(u64 v) {
    float lo, hi;
    asm("mov.b64 {%0, %1}, %2;" : "=f"(lo), "=f"(hi) : "l"(v));
    return lo + hi;
}

// ---------------- shared memory layouts ----------------------------------------------
struct __align__(16) TileSm {
    float Xa[16][MDIM];
    float Xb[16][MDIM];
    float EF[16][4];
};
struct LvlS {
    int level[BATCH];
    int off[BATCH + 2];
    int cnt[BATCH + 2];
    int maxl;
    int changed;
};
#define SMEM_BYTES ((int)(sizeof(LvlS) > sizeof(TileSm) ? sizeof(LvlS) : sizeof(TileSm)))

extern __shared__ __align__(16) char smem_raw[];

__device__ __forceinline__ float sigmoidf_(float x) { return 1.0f / (1.0f + expf(-x)); }

// ---------------- per-level phase-parallel pipeline ----------------------------------
template<int R>
__device__ void run_level(int lvS, int lvE,
                          const float* __restrict__ b1,
                          const float* __restrict__ bhh,
                          float* __restrict__ out)
{
    const int TMR = 2 * R;
    const int tid = threadIdx.x;
    const int nE = lvE - lvS;
    const int nchunk = (nE + TMR - 1) / TMR;
    TileSm* Sx = (TileSm*)smem_raw;
    const ulonglong2* w1a2 = (const ulonglong2*)g_W1tA;
    const ulonglong2* w1b2 = (const ulonglong2*)g_W1tB;
    const ulonglong2* whh2 = (const ulonglong2*)g_whht;
    const ulonglong2* wct2 = (const ulonglong2*)g_Wct;

    // ---- P1: H1 (type 0) + GHs (types 1-3) + GHd (types 4-6)
    for (int u = blockIdx.x; u < 7 * nchunk; u += gridDim.x) {
        int chunk = u / 7, type = u - chunk * 7;
        int base = lvS + chunk * TMR;
        int cnt = min(TMR, lvE - base);
        __syncthreads();
        if (type == 0) {
            for (int i = tid; i < TMR * MDIM; i += NT) {
                int m = i >> 8, c = i & 255;
                float xs = 0.f, xd = 0.f;
                if (m < cnt) {
                    int p = base + m;
                    xs = out[(size_t)g_pS[p] * MDIM + c] * g_pFs[p];
                    xd = out[(size_t)g_pD[p] * MDIM + c] * g_pFd[p];
                }
                Sx->Xa[m][c] = xs;
                Sx->Xb[m][c] = xd;
            }
            if (tid < TMR) {
                int m = tid;
                float e0 = 0.f, e1 = 0.f, e2 = 0.f;
                if (m < cnt) {
                    int p = base + m;
                    e0 = g_pEF[3 * p]; e1 = g_pEF[3 * p + 1]; e2 = g_pEF[3 * p + 2];
                }
                Sx->EF[m][0] = e0; Sx->EF[m][1] = e1; Sx->EF[m][2] = e2; Sx->EF[m][3] = 0.f;
            }
            __syncthreads();
            int c = tid & 255, m0 = (tid >> 8) * R;
            u64 acc[R];
            #pragma unroll
            for (int r = 0; r < R; r++) acc[r] = 0ull;
            #pragma unroll 2
            for (int k4 = 0; k4 < 64; k4++) {
                ulonglong2 w = w1a2[k4 * MDIM + c];
                #pragma unroll
                for (int r = 0; r < R; r++) {
                    ulonglong2 x = ((const ulonglong2*)Sx->Xa[m0 + r])[k4];
                    acc[r] = ffma2(x.x, w.x, acc[r]);
                    acc[r] = ffma2(x.y, w.y, acc[r]);
                }
            }
            #pragma unroll 2
            for (int k4 = 0; k4 < 64; k4++) {
                ulonglong2 w = w1b2[k4 * MDIM + c];
                #pragma unroll
                for (int r = 0; r < R; r++) {
                    ulonglong2 x = ((const ulonglong2*)Sx->Xb[m0 + r])[k4];
                    acc[r] = ffma2(x.x, w.x, acc[r]);
                    acc[r] = ffma2(x.y, w.y, acc[r]);
                }
            }
            float w0 = g_W1te[c], w1 = g_W1te[MDIM + c], w2 = g_W1te[2 * MDIM + c];
            float bb = b1[c];
            #pragma unroll
            for (int r = 0; r < R; r++) {
                float a = pair_sum(acc[r]) + bb;
                a = fmaf(Sx->EF[m0 + r][0], w0, a);
                a = fmaf(Sx->EF[m0 + r][1], w1, a);
                a = fmaf(Sx->EF[m0 + r][2], w2, a);
                if (m0 + r < cnt)
                    g_H1[(size_t)(base + m0 + r) * MDIM + c] = fmaxf(a, 0.f);
            }
        } else {
            int t = type - 1;
            int isD = t >= 3;
            int cb = isD ? (t - 3) : t;
            for (int i = tid; i < TMR * MDIM; i += NT) {
                int m = i >> 8, c = i & 255;
                float x = 0.f;
                if (m < cnt) {
                    int p = base + m;
                    x = isD ? out[(size_t)g_pD[p] * MDIM + c] * g_pFd[p]
                            : out[(size_t)g_pS[p] * MDIM + c] * g_pFs[p];
                }
                Sx->Xa[m][c] = x;
            }
            __syncthreads();
            int cl = tid & 255, m0 = (tid >> 8) * R;
            int c = cb * MDIM + cl;
            u64 acc[R];
            #pragma unroll
            for (int r = 0; r < R; r++) acc[r] = 0ull;
            #pragma unroll 2
            for (int k4 = 0; k4 < 64; k4++) {
                ulonglong2 w = whh2[k4 * G3DIM + c];
                #pragma unroll
                for (int r = 0; r < R; r++) {
                    ulonglong2 x = ((const ulonglong2*)Sx->Xa[m0 + r])[k4];
                    acc[r] = ffma2(x.x, w.x, acc[r]);
                    acc[r] = ffma2(x.y, w.y, acc[r]);
                }
            }
            float* dstGH = isD ? g_GHd : g_GHs;
            float bb = bhh[c];
            #pragma unroll
            for (int r = 0; r < R; r++)
                if (m0 + r < cnt)
                    dstGH[(size_t)(base + m0 + r) * G3DIM + c] = pair_sum(acc[r]) + bb;
        }
    }
    grid_sync();

    // ---- P2: GI = H1 @ Wc^T + bc  (3 col-blocks per chunk)
    for (int u = blockIdx.x; u < 3 * nchunk; u += gridDim.x) {
        int chunk = u / 3, cb = u - chunk * 3;
        int base = lvS + chunk * TMR;
        int cnt = min(TMR, lvE - base);
        __syncthreads();
        for (int i = tid; i < TMR * MDIM; i += NT) {
            int m = i >> 8, c = i & 255;
            Sx->Xa[m][c] = (m < cnt) ? g_H1[(size_t)(base + m) * MDIM + c] : 0.f;
        }
        __syncthreads();
        int cl = tid & 255, m0 = (tid >> 8) * R;
        int c = cb * MDIM + cl;
        u64 acc[R];
        #pragma unroll
        for (int r = 0; r < R; r++) acc[r] = 0ull;
        #pragma unroll 2
        for (int k4 = 0; k4 < 64; k4++) {
            ulonglong2 w = wct2[k4 * G3DIM + c];
            #pragma unroll
            for (int r = 0; r < R; r++) {
                ulonglong2 x = ((const ulonglong2*)Sx->Xa[m0 + r])[k4];
                acc[r] = ffma2(x.x, w.x, acc[r]);
                acc[r] = ffma2(x.y, w.y, acc[r]);
            }
        }
        float bb = g_bc[c];
        #pragma unroll
        for (int r = 0; r < R; r++)
            if (m0 + r < cnt)
                g_GI[(size_t)(base + m0 + r) * G3DIM + c] = pair_sum(acc[r]) + bb;
    }
    grid_sync();

    // ---- P3: GRU elementwise + scatter
    for (int idx = blockIdx.x * NT + tid; idx < nE * MDIM; idx += gridDim.x * NT) {
        int pl = idx >> 8, j = idx & 255;
        int p = lvS + pl;
        int s = g_pS[p], d = g_pD[p];
        float hs = out[(size_t)s * MDIM + j] * g_pFs[p];
        float hd = out[(size_t)d * MDIM + j] * g_pFd[p];
        const float* gi  = g_GI  + (size_t)p * G3DIM;
        const float* ghs = g_GHs + (size_t)p * G3DIM;
        const float* ghd = g_GHd + (size_t)p * G3DIM;
        float gir = gi[j], giz = gi[MDIM + j], gin = gi[2 * MDIM + j];
        float rr = sigmoidf_(gir + ghs[j]);
        float zz = sigmoidf_(giz + ghs[MDIM + j]);
        float nn = tanhf(gin + rr * ghs[2 * MDIM + j]);
        float us = (1.0f - zz) * nn + zz * hs;
        rr = sigmoidf_(gir + ghd[j]);
        zz = sigmoidf_(giz + ghd[MDIM + j]);
        nn = tanhf(gin + rr * ghd[2 * MDIM + j]);
        float ud = (1.0f - zz) * nn + zz * hd;
        if (s != d) out[(size_t)s * MDIM + j] = us;   // dst wins when s==d
        out[(size_t)d * MDIM + j] = ud;
    }
    grid_sync();
}

__global__ void __launch_bounds__(NT, 1)
tgn_kernel(const int* __restrict__ src, const int* __restrict__ dst,
           const float* __restrict__ ef, const int* __restrict__ ts,
           const float* __restrict__ mem0, const float* __restrict__ lu0,
           const float* __restrict__ W1, const float* __restrict__ b1,
           const float* __restrict__ W2, const float* __restrict__ b2,
           const float* __restrict__ wih, const float* __restrict__ bih,
           const float* __restrict__ whh, const float* __restrict__ bhh,
           float* __restrict__ out)
{
    const int tid     = threadIdx.x;
    const int gtid    = blockIdx.x * NT + tid;
    const int gstride = gridDim.x * NT;

    // ---------- Phase A: copy memory -> out; weight transforms; counters -------------
    {
        const float4* s4 = (const float4*)mem0;
        float4*       d4 = (float4*)out;
        const int n4 = NNODES * MDIM / 4;
        for (int i = gtid; i < n4; i += gstride) d4[i] = s4[i];
        for (int i = gtid; i < NNODES; i += gstride) g_ncnt[i] = 0;

        for (int i = gtid; i < MDIM * MDIM; i += gstride) {
            int k4 = i >> 10, rem = i & 1023, c = rem >> 2, ks = rem & 3;
            int k = k4 * 4 + ks;
            g_W1tA[i] = W1[(size_t)c * INENC + k];
            g_W1tB[i] = W1[(size_t)c * INENC + MDIM + k];
        }
        for (int i = gtid; i < G3DIM * MDIM; i += gstride) {
            int k4 = i / 3072, rem = i - k4 * 3072, c = rem >> 2, ks = rem & 3;
            int k = k4 * 4 + ks;
            g_whht[i] = whh[(size_t)c * MDIM + k];
        }
        for (int i = gtid; i < 3 * MDIM; i += gstride) {
            int k = i >> 8, c = i & 255;
            g_W1te[i] = W1[(size_t)c * INENC + 2 * MDIM + k];
        }
        // Wc = wih @ W2 (packed), bc = bih + wih @ b2
        for (int i = gtid; i < G3DIM * (MDIM / 4); i += gstride) {
            int c = i >> 6, k4 = i & 63;
            float4 a = make_float4(0.f, 0.f, 0.f, 0.f);
            const float*  wr  = wih + (size_t)c * MDIM;
            const float4* w2r = (const float4*)W2;
            for (int j = 0; j < MDIM; j++) {
                float wv = wr[j];
                float4 b = w2r[j * 64 + k4];
                a.x = fmaf(wv, b.x, a.x);
                a.y = fmaf(wv, b.y, a.y);
                a.z = fmaf(wv, b.z, a.z);
                a.w = fmaf(wv, b.w, a.w);
            }
            float* dstp = g_Wct + (size_t)k4 * 3072 + c * 4;
            dstp[0] = a.x; dstp[1] = a.y; dstp[2] = a.z; dstp[3] = a.w;
        }
        for (int c = gtid; c < G3DIM; c += gstride) {
            float acc = bih[c];
            const float* wr = wih + (size_t)c * MDIM;
            for (int j = 0; j < MDIM; j++) acc = fmaf(wr[j], b2[j], acc);
            g_bc[c] = acc;
        }
    }
    grid_sync();

    // ---------- Phase A2: per-node occurrence buckets ---------------------------------
    for (int i = gtid; i < 2 * BATCH; i += gstride) {
        int e = i >> 1;
        int v = (i & 1) ? dst[e] : src[e];
        int slot = atomicAdd(&g_ncnt[v], 1);
        if (slot < BK) g_nbuck[v * BK + slot] = i;
    }
    grid_sync();

    // ---------- Phase A3: predecessor endpoint + decay factor -------------------------
    for (int i = gtid; i < 2 * BATCH; i += gstride) {
        int e = i >> 1;
        int v = (i & 1) ? dst[e] : src[e];
        int lim = e << 1;
        int cmax = min(g_ncnt[v], BK);
        int p = -1;
        for (int t = 0; t < cmax; t++) {
            int j = g_nbuck[v * BK + t];
            if (j < lim && j > p) p = j;
        }
        g_pred[i] = p;
        float prev_t = (p >= 0) ? (float)ts[p >> 1] : lu0[v];
        float dt = fmaxf((float)ts[e] - prev_t, 0.f);
        g_F[i] = expf(-0.1f * dt);
    }
    grid_sync();

    // ---------- Phase B (block 0): levelize + sort + permuted metadata ----------------
    if (blockIdx.x == 0) {
        LvlS* L = (LvlS*)smem_raw;
        for (int e = tid; e < BATCH; e += NT) L->level[e] = 0;
        if (tid == 0) L->maxl = 0;
        __syncthreads();
        for (;;) {
            if (tid == 0) L->changed = 0;
            __syncthreads();
            for (int e = tid; e < BATCH; e += NT) {
                int ps = g_pred[2 * e], pd = g_pred[2 * e + 1];
                int lv = 0;
                if (ps >= 0) { int t = L->level[ps >> 1] + 1; if (t > lv) lv = t; }
                if (pd >= 0) { int t = L->level[pd >> 1] + 1; if (t > lv) lv = t; }
                if (lv > L->level[e]) { L->level[e] = lv; L->changed = 1; }
            }
            __syncthreads();
            int ch = L->changed;
            __syncthreads();
            if (!ch) break;
        }
        for (int e = tid; e < BATCH; e += NT) atomicMax(&L->maxl, L->level[e]);
        __syncthreads();
        int nl = L->maxl + 1;
        for (int i = tid; i < nl + 1; i += NT) L->cnt[i] = 0;
        __syncthreads();
        for (int e = tid; e < BATCH; e += NT) atomicAdd(&L->cnt[L->level[e]], 1);
        __syncthreads();
        if (tid == 0) {
            int acc = 0;
            for (int l = 0; l < nl; l++) { L->off[l] = acc; acc += L->cnt[l]; }
            L->off[nl] = acc;
            g_nlevels = nl;
            for (int l = 0; l <= nl; l++) g_lvl_start[l] = L->off[l];
        }
        __syncthreads();
        for (int i = tid; i < nl; i += NT) L->cnt[i] = 0;
        __syncthreads();
        for (int e = tid; e < BATCH; e += NT) {
            int l = L->level[e];
            int pos = L->off[l] + atomicAdd(&L->cnt[l], 1);
            g_evlist[pos] = e;
        }
        __syncthreads();
        for (int p = tid; p < BATCH; p += NT) {
            int e = g_evlist[p];
            g_pS[p] = src[e];
            g_pD[p] = dst[e];
            g_pFs[p] = g_F[2 * e];
            g_pFd[p] = g_F[2 * e + 1];
            g_pEF[3 * p]     = ef[3 * e];
            g_pEF[3 * p + 1] = ef[3 * e + 1];
            g_pEF[3 * p + 2] = ef[3 * e + 2];
        }
    }
    grid_sync();

    // ---------- Phase C: per-level phase-parallel pipeline ----------------------------
    const int nlevels = g_nlevels;
    for (int lvl = 0; lvl < nlevels; lvl++) {
        int lvS = g_lvl_start[lvl];
        int lvE = g_lvl_start[lvl + 1];
        if (lvE - lvS <= 32) run_level<2>(lvS, lvE, b1, bhh, out);
        else                 run_level<8>(lvS, lvE, b1, bhh, out);
    }
}

extern "C" void kernel_launch(void* const* d_in, const int* in_sizes, int n_in,
                              void* d_out, int out_size)
{
    const int*   src  = (const int*)  d_in[0];
    const int*   dst  = (const int*)  d_in[1];
    const float* ef   = (const float*)d_in[2];
    const int*   ts   = (const int*)  d_in[3];
    const float* mem0 = (const float*)d_in[4];
    const float* lu0  = (const float*)d_in[5];
    const float* W1   = (const float*)d_in[6];
    const float* b1   = (const float*)d_in[7];
    const float* W2   = (const float*)d_in[8];
    const float* b2   = (const float*)d_in[9];
    const float* wih  = (const float*)d_in[10];
    const float* whh  = (const float*)d_in[11];
    const float* bih  = (const float*)d_in[12];
    const float* bhh  = (const float*)d_in[13];
    float* out = (float*)d_out;

    int dev = 0, sms = 148;
    cudaGetDevice(&dev);
    cudaDeviceGetAttribute(&sms, cudaDevAttrMultiProcessorCount, dev);
    if (sms <= 0) sms = 148;

    cudaFuncSetAttribute(tgn_kernel, cudaFuncAttributeMaxDynamicSharedMemorySize, SMEM_BYTES);

    tgn_kernel<<<sms, NT, SMEM_BYTES>>>(src, dst, ef, ts, mem0, lu0,
                                        W1, b1, W2, b2, wih, bih, whh, bhh, out);
}

// round 8
// speedup vs baseline: 1.0211x; 1.0211x over previous
#include <cuda_runtime.h>
#include <math.h>

#define NNODES 100000
#define BATCH  4096
#define MDIM   256
#define G3DIM  768
#define INENC  515
#define NT     512
#define BK     16

typedef unsigned long long u64;

// ---------------- device scratch (rebuilt every launch; graph-replay safe) -----------
__device__ int      g_ncnt[NNODES];
__device__ int      g_nbuck[NNODES * BK];
__device__ int      g_pred[2 * BATCH];
__device__ float    g_F[2 * BATCH];
__device__ int      g_evlist[BATCH];
__device__ int      g_lvl_start[BATCH + 2];
__device__ int      g_nlevels;
__device__ unsigned g_bar_count = 0;
__device__ unsigned g_bar_gen   = 0;

__device__ int   g_pS[BATCH], g_pD[BATCH];
__device__ float g_pFs[BATCH], g_pFd[BATCH];
__device__ float g_pEF[BATCH * 3];

__device__ __align__(16) float g_H1 [BATCH * MDIM];
__device__ __align__(16) float g_GI [BATCH * G3DIM];
__device__ __align__(16) float g_GHs[BATCH * G3DIM];
__device__ __align__(16) float g_GHd[BATCH * G3DIM];

// transposed+packed weights: layout [k4][c][4] (16B per (k4,c))
__device__ __align__(16) float g_W1tA[MDIM * MDIM];
__device__ __align__(16) float g_W1tB[MDIM * MDIM];
__device__ __align__(16) float g_W1te[3 * MDIM];
__device__ __align__(16) float g_whht[G3DIM * MDIM];
__device__ __align__(16) float g_Wct [G3DIM * MDIM];
__device__ __align__(16) float g_bc  [G3DIM];

// ---------------- software grid barrier (all CTAs resident by construction) ----------
__device__ __forceinline__ void grid_sync() {
    __syncthreads();
    if (threadIdx.x == 0) {
        __threadfence();
        unsigned gen = *((volatile unsigned*)&g_bar_gen);
        if (atomicAdd(&g_bar_count, 1u) == gridDim.x - 1u) {
            *((volatile unsigned*)&g_bar_count) = 0u;
            __threadfence();
            atomicAdd(&g_bar_gen, 1u);
        } else {
            while (*((volatile unsigned*)&g_bar_gen) == gen) { __nanosleep(64); }
        }
        __threadfence();
    }
    __syncthreads();
}

// ---------------- packed f32x2 helpers ------------------------------------------------
__device__ __forceinline__ u64 ffma2(u64 a, u64 b, u64 c) {
    u64 d;
    asm("fma.rn.f32x2 %0, %1, %2, %3;" : "=l"(d) : "l"(a), "l"(b), "l"(c));
    return d;
}
__device__ __forceinline__ float pair_sum(u64 v) {
    float lo, hi;
    asm("mov.b64 {%0, %1}, %2;" : "=f"(lo), "=f"(hi) : "l"(v));
    return lo + hi;
}

// ---------------- shared memory layouts ----------------------------------------------
struct __align__(16) TileSm {
    float Xa[8][MDIM];
    float Xb[8][MDIM];
    float EF[8][4];
};
struct LvlS {
    int level[BATCH];
    int off[BATCH + 2];
    int cnt[BATCH + 2];
    int maxl;
    int changed;
};
#define SMEM_BYTES ((int)(sizeof(LvlS) > sizeof(TileSm) ? sizeof(LvlS) : sizeof(TileSm)))

extern __shared__ __align__(16) char smem_raw[];

__device__ __forceinline__ float sigmoidf_(float x) { return 1.0f / (1.0f + expf(-x)); }

// ---------------- per-level phase-parallel pipeline ----------------------------------
// R rows per 256-thread group; tile height TMR = 2*R (<= 8).
template<int R>
__device__ void run_level(int lvS, int lvE,
                          const float* __restrict__ b1,
                          const float* __restrict__ bhh,
                          float* __restrict__ out)
{
    const int TMR = 2 * R;
    const int tid = threadIdx.x;
    const int nE = lvE - lvS;
    const int nchunk = (nE + TMR - 1) / TMR;
    TileSm* Sx = (TileSm*)smem_raw;
    const ulonglong2* w1a2 = (const ulonglong2*)g_W1tA;
    const ulonglong2* w1b2 = (const ulonglong2*)g_W1tB;
    const ulonglong2* whh2 = (const ulonglong2*)g_whht;
    const ulonglong2* wct2 = (const ulonglong2*)g_Wct;

    // ---- P1: 4 units per chunk.  type 0: H1.  types 1-3: GH col-block (src+dst fused)
    for (int u = blockIdx.x; u < 4 * nchunk; u += gridDim.x) {
        int chunk = u >> 2, type = u & 3;
        int base = lvS + chunk * TMR;
        int cnt = min(TMR, lvE - base);
        __syncthreads();
        // gather decayed Xs -> Xa, Xd -> Xb (needed by every unit type)
        for (int i = tid; i < TMR * MDIM; i += NT) {
            int m = i >> 8, c = i & 255;
            float xs = 0.f, xd = 0.f;
            if (m < cnt) {
                int p = base + m;
                xs = out[(size_t)g_pS[p] * MDIM + c] * g_pFs[p];
                xd = out[(size_t)g_pD[p] * MDIM + c] * g_pFd[p];
            }
            Sx->Xa[m][c] = xs;
            Sx->Xb[m][c] = xd;
        }
        if (type == 0 && tid < TMR) {
            int m = tid;
            float e0 = 0.f, e1 = 0.f, e2 = 0.f;
            if (m < cnt) {
                int p = base + m;
                e0 = g_pEF[3 * p]; e1 = g_pEF[3 * p + 1]; e2 = g_pEF[3 * p + 2];
            }
            Sx->EF[m][0] = e0; Sx->EF[m][1] = e1; Sx->EF[m][2] = e2; Sx->EF[m][3] = 0.f;
        }
        __syncthreads();

        if (type == 0) {
            int c = tid & 255, m0 = (tid >> 8) * R;
            u64 acc[R];
            #pragma unroll
            for (int r = 0; r < R; r++) acc[r] = 0ull;
            #pragma unroll 2
            for (int k4 = 0; k4 < 64; k4++) {
                ulonglong2 wA = w1a2[k4 * MDIM + c];
                ulonglong2 wB = w1b2[k4 * MDIM + c];
                #pragma unroll
                for (int r = 0; r < R; r++) {
                    ulonglong2 xa = ((const ulonglong2*)Sx->Xa[m0 + r])[k4];
                    ulonglong2 xb = ((const ulonglong2*)Sx->Xb[m0 + r])[k4];
                    acc[r] = ffma2(xa.x, wA.x, acc[r]);
                    acc[r] = ffma2(xa.y, wA.y, acc[r]);
                    acc[r] = ffma2(xb.x, wB.x, acc[r]);
                    acc[r] = ffma2(xb.y, wB.y, acc[r]);
                }
            }
            float w0 = g_W1te[c], w1 = g_W1te[MDIM + c], w2 = g_W1te[2 * MDIM + c];
            float bb = b1[c];
            #pragma unroll
            for (int r = 0; r < R; r++) {
                float a = pair_sum(acc[r]) + bb;
                a = fmaf(Sx->EF[m0 + r][0], w0, a);
                a = fmaf(Sx->EF[m0 + r][1], w1, a);
                a = fmaf(Sx->EF[m0 + r][2], w2, a);
                if (m0 + r < cnt)
                    g_H1[(size_t)(base + m0 + r) * MDIM + c] = fmaxf(a, 0.f);
            }
        } else {
            int cb = type - 1;
            int cl = tid & 255, m0 = (tid >> 8) * R;
            int c = cb * MDIM + cl;
            u64 accS[R], accD[R];
            #pragma unroll
            for (int r = 0; r < R; r++) { accS[r] = 0ull; accD[r] = 0ull; }
            #pragma unroll 2
            for (int k4 = 0; k4 < 64; k4++) {
                ulonglong2 w = whh2[k4 * G3DIM + c];
                #pragma unroll
                for (int r = 0; r < R; r++) {
                    ulonglong2 xa = ((const ulonglong2*)Sx->Xa[m0 + r])[k4];
                    ulonglong2 xb = ((const ulonglong2*)Sx->Xb[m0 + r])[k4];
                    accS[r] = ffma2(xa.x, w.x, accS[r]);
                    accS[r] = ffma2(xa.y, w.y, accS[r]);
                    accD[r] = ffma2(xb.x, w.x, accD[r]);
                    accD[r] = ffma2(xb.y, w.y, accD[r]);
                }
            }
            float bb = bhh[c];
            #pragma unroll
            for (int r = 0; r < R; r++) {
                if (m0 + r < cnt) {
                    g_GHs[(size_t)(base + m0 + r) * G3DIM + c] = pair_sum(accS[r]) + bb;
                    g_GHd[(size_t)(base + m0 + r) * G3DIM + c] = pair_sum(accD[r]) + bb;
                }
            }
        }
    }
    grid_sync();

    // ---- P2: GI = H1 @ Wc^T + bc  (3 col-blocks per chunk)
    for (int u = blockIdx.x; u < 3 * nchunk; u += gridDim.x) {
        int chunk = u / 3, cb = u - chunk * 3;
        int base = lvS + chunk * TMR;
        int cnt = min(TMR, lvE - base);
        __syncthreads();
        for (int i = tid; i < TMR * MDIM; i += NT) {
            int m = i >> 8, c = i & 255;
            Sx->Xa[m][c] = (m < cnt) ? g_H1[(size_t)(base + m) * MDIM + c] : 0.f;
        }
        __syncthreads();
        int cl = tid & 255, m0 = (tid >> 8) * R;
        int c = cb * MDIM + cl;
        u64 acc[R];
        #pragma unroll
        for (int r = 0; r < R; r++) acc[r] = 0ull;
        #pragma unroll 2
        for (int k4 = 0; k4 < 64; k4++) {
            ulonglong2 w = wct2[k4 * G3DIM + c];
            #pragma unroll
            for (int r = 0; r < R; r++) {
                ulonglong2 x = ((const ulonglong2*)Sx->Xa[m0 + r])[k4];
                acc[r] = ffma2(x.x, w.x, acc[r]);
                acc[r] = ffma2(x.y, w.y, acc[r]);
            }
        }
        float bb = g_bc[c];
        #pragma unroll
        for (int r = 0; r < R; r++)
            if (m0 + r < cnt)
                g_GI[(size_t)(base + m0 + r) * G3DIM + c] = pair_sum(acc[r]) + bb;
    }
    grid_sync();

    // ---- P3: GRU elementwise + scatter
    for (int idx = blockIdx.x * NT + tid; idx < nE * MDIM; idx += gridDim.x * NT) {
        int pl = idx >> 8, j = idx & 255;
        int p = lvS + pl;
        int s = g_pS[p], d = g_pD[p];
        float hs = out[(size_t)s * MDIM + j] * g_pFs[p];
        float hd = out[(size_t)d * MDIM + j] * g_pFd[p];
        const float* gi  = g_GI  + (size_t)p * G3DIM;
        const float* ghs = g_GHs + (size_t)p * G3DIM;
        const float* ghd = g_GHd + (size_t)p * G3DIM;
        float gir = gi[j], giz = gi[MDIM + j], gin = gi[2 * MDIM + j];
        float rr = sigmoidf_(gir + ghs[j]);
        float zz = sigmoidf_(giz + ghs[MDIM + j]);
        float nn = tanhf(gin + rr * ghs[2 * MDIM + j]);
        float us = (1.0f - zz) * nn + zz * hs;
        rr = sigmoidf_(gir + ghd[j]);
        zz = sigmoidf_(giz + ghd[MDIM + j]);
        nn = tanhf(gin + rr * ghd[2 * MDIM + j]);
        float ud = (1.0f - zz) * nn + zz * hd;
        if (s != d) out[(size_t)s * MDIM + j] = us;   // dst wins when s==d
        out[(size_t)d * MDIM + j] = ud;
    }
    grid_sync();
}

__global__ void __launch_bounds__(NT, 2)
tgn_kernel(const int* __restrict__ src, const int* __restrict__ dst,
           const float* __restrict__ ef, const int* __restrict__ ts,
           const float* __restrict__ mem0, const float* __restrict__ lu0,
           const float* __restrict__ W1, const float* __restrict__ b1,
           const float* __restrict__ W2, const float* __restrict__ b2,
           const float* __restrict__ wih, const float* __restrict__ bih,
           const float* __restrict__ whh, const float* __restrict__ bhh,
           float* __restrict__ out)
{
    const int tid     = threadIdx.x;
    const int gtid    = blockIdx.x * NT + tid;
    const int gstride = gridDim.x * NT;

    // ---------- Phase A: copy memory -> out; weight transforms; counters -------------
    {
        const float4* s4 = (const float4*)mem0;
        float4*       d4 = (float4*)out;
        const int n4 = NNODES * MDIM / 4;
        for (int i = gtid; i < n4; i += gstride) d4[i] = s4[i];
        for (int i = gtid; i < NNODES; i += gstride) g_ncnt[i] = 0;

        for (int i = gtid; i < MDIM * MDIM; i += gstride) {
            int k4 = i >> 10, rem = i & 1023, c = rem >> 2, ks = rem & 3;
            int k = k4 * 4 + ks;
            g_W1tA[i] = W1[(size_t)c * INENC + k];
            g_W1tB[i] = W1[(size_t)c * INENC + MDIM + k];
        }
        for (int i = gtid; i < G3DIM * MDIM; i += gstride) {
            int k4 = i / 3072, rem = i - k4 * 3072, c = rem >> 2, ks = rem & 3;
            int k = k4 * 4 + ks;
            g_whht[i] = whh[(size_t)c * MDIM + k];
        }
        for (int i = gtid; i < 3 * MDIM; i += gstride) {
            int k = i >> 8, c = i & 255;
            g_W1te[i] = W1[(size_t)c * INENC + 2 * MDIM + k];
        }
        // Wc = wih @ W2 (packed), bc = bih + wih @ b2
        for (int i = gtid; i < G3DIM * (MDIM / 4); i += gstride) {
            int c = i >> 6, k4 = i & 63;
            float4 a = make_float4(0.f, 0.f, 0.f, 0.f);
            const float*  wr  = wih + (size_t)c * MDIM;
            const float4* w2r = (const float4*)W2;
            for (int j = 0; j < MDIM; j++) {
                float wv = wr[j];
                float4 b = w2r[j * 64 + k4];
                a.x = fmaf(wv, b.x, a.x);
                a.y = fmaf(wv, b.y, a.y);
                a.z = fmaf(wv, b.z, a.z);
                a.w = fmaf(wv, b.w, a.w);
            }
            float* dstp = g_Wct + (size_t)k4 * 3072 + c * 4;
            dstp[0] = a.x; dstp[1] = a.y; dstp[2] = a.z; dstp[3] = a.w;
        }
        for (int c = gtid; c < G3DIM; c += gstride) {
            float acc = bih[c];
            const float* wr = wih + (size_t)c * MDIM;
            for (int j = 0; j < MDIM; j++) acc = fmaf(wr[j], b2[j], acc);
            g_bc[c] = acc;
        }
    }
    grid_sync();

    // ---------- Phase A2: per-node occurrence buckets ---------------------------------
    for (int i = gtid; i < 2 * BATCH; i += gstride) {
        int e = i >> 1;
        int v = (i & 1) ? dst[e] : src[e];
        int slot = atomicAdd(&g_ncnt[v], 1);
        if (slot < BK) g_nbuck[v * BK + slot] = i;
    }
    grid_sync();

    // ---------- Phase A3: predecessor endpoint + decay factor -------------------------
    for (int i = gtid; i < 2 * BATCH; i += gstride) {
        int e = i >> 1;
        int v = (i & 1) ? dst[e] : src[e];
        int lim = e << 1;
        int cmax = min(g_ncnt[v], BK);
        int p = -1;
        for (int t = 0; t < cmax; t++) {
            int j = g_nbuck[v * BK + t];
            if (j < lim && j > p) p = j;
        }
        g_pred[i] = p;
        float prev_t = (p >= 0) ? (float)ts[p >> 1] : lu0[v];
        float dt = fmaxf((float)ts[e] - prev_t, 0.f);
        g_F[i] = expf(-0.1f * dt);
    }
    grid_sync();

    // ---------- Phase B (block 0): levelize + sort + permuted metadata ----------------
    if (blockIdx.x == 0) {
        LvlS* L = (LvlS*)smem_raw;
        for (int e = tid; e < BATCH; e += NT) L->level[e] = 0;
        if (tid == 0) L->maxl = 0;
        __syncthreads();
        for (;;) {
            if (tid == 0) L->changed = 0;
            __syncthreads();
            for (int e = tid; e < BATCH; e += NT) {
                int ps = g_pred[2 * e], pd = g_pred[2 * e + 1];
                int lv = 0;
                if (ps >= 0) { int t = L->level[ps >> 1] + 1; if (t > lv) lv = t; }
                if (pd >= 0) { int t = L->level[pd >> 1] + 1; if (t > lv) lv = t; }
                if (lv > L->level[e]) { L->level[e] = lv; L->changed = 1; }
            }
            __syncthreads();
            int ch = L->changed;
            __syncthreads();
            if (!ch) break;
        }
        for (int e = tid; e < BATCH; e += NT) atomicMax(&L->maxl, L->level[e]);
        __syncthreads();
        int nl = L->maxl + 1;
        for (int i = tid; i < nl + 1; i += NT) L->cnt[i] = 0;
        __syncthreads();
        for (int e = tid; e < BATCH; e += NT) atomicAdd(&L->cnt[L->level[e]], 1);
        __syncthreads();
        if (tid == 0) {
            int acc = 0;
            for (int l = 0; l < nl; l++) { L->off[l] = acc; acc += L->cnt[l]; }
            L->off[nl] = acc;
            g_nlevels = nl;
            for (int l = 0; l <= nl; l++) g_lvl_start[l] = L->off[l];
        }
        __syncthreads();
        for (int i = tid; i < nl; i += NT) L->cnt[i] = 0;
        __syncthreads();
        for (int e = tid; e < BATCH; e += NT) {
            int l = L->level[e];
            int pos = L->off[l] + atomicAdd(&L->cnt[l], 1);
            g_evlist[pos] = e;
        }
        __syncthreads();
        for (int p = tid; p < BATCH; p += NT) {
            int e = g_evlist[p];
            g_pS[p] = src[e];
            g_pD[p] = dst[e];
            g_pFs[p] = g_F[2 * e];
            g_pFd[p] = g_F[2 * e + 1];
            g_pEF[3 * p]     = ef[3 * e];
            g_pEF[3 * p + 1] = ef[3 * e + 1];
            g_pEF[3 * p + 2] = ef[3 * e + 2];
        }
    }
    grid_sync();

    // ---------- Phase C: per-level phase-parallel pipeline ----------------------------
    const int nlevels = g_nlevels;
    for (int lvl = 0; lvl < nlevels; lvl++) {
        int lvS = g_lvl_start[lvl];
        int lvE = g_lvl_start[lvl + 1];
        if (lvE - lvS <= 64) run_level<1>(lvS, lvE, b1, bhh, out);
        else                 run_level<4>(lvS, lvE, b1, bhh, out);
    }
}

extern "C" void kernel_launch(void* const* d_in, const int* in_sizes, int n_in,
                              void* d_out, int out_size)
{
    const int*   src  = (const int*)  d_in[0];
    const int*   dst  = (const int*)  d_in[1];
    const float* ef   = (const float*)d_in[2];
    const int*   ts   = (const int*)  d_in[3];
    const float* mem0 = (const float*)d_in[4];
    const float* lu0  = (const float*)d_in[5];
    const float* W1   = (const float*)d_in[6];
    const float* b1   = (const float*)d_in[7];
    const float* W2   = (const float*)d_in[8];
    const float* b2   = (const float*)d_in[9];
    const float* wih  = (const float*)d_in[10];
    const float* whh  = (const float*)d_in[11];
    const float* bih  = (const float*)d_in[12];
    const float* bhh  = (const float*)d_in[13];
    float* out = (float*)d_out;

    int dev = 0, sms = 148;
    cudaGetDevice(&dev);
    cudaDeviceGetAttribute(&sms, cudaDevAttrMultiProcessorCount, dev);
    if (sms <= 0) sms = 148;

    cudaFuncSetAttribute(tgn_kernel, cudaFuncAttributeMaxDynamicSharedMemorySize, SMEM_BYTES);

    // Deadlock-proof grid sizing: only launch as many CTAs as are guaranteed
    // co-resident (the software grid barrier requires full residency).
    int occ = 0;
    cudaOccupancyMaxActiveBlocksPerMultiprocessor(&occ, tgn_kernel, NT, SMEM_BYTES);
    if (occ < 1) occ = 1;
    if (occ > 2) occ = 2;

    tgn_kernel<<<occ * sms, NT, SMEM_BYTES>>>(src, dst, ef, ts, mem0, lu0,
                                              W1, b1, W2, b2, wih, bih, whh, bhh, out);
}